// round 12
// baseline (speedup 1.0000x reference)
#include <cuda_runtime.h>
#include <cuda_fp16.h>
#include <cstdint>

#define NN 8192
#define DIN 512
#define DOUT 64
#define HEADS 8
#define MWORDS 256
#define L2E 1.44269504088896f
#define ONE2 0x3C003C00u
#define PSCALE 12.0f   // p scaled by 2^12: lifts fp16 operands out of denormal range

typedef unsigned long long ull;

__device__ __half   g_WhH[HEADS * 64 * NN];  // [h][d][j perm16] fp16
__device__ float    g_xr[NN * DIN];          // tf32-rounded x
__device__ float    g_Wr[HEADS * DIN * DOUT];// tf32-rounded W
__device__ float2   g_w12[HEADS * DIN];      // (W@a1, W@a2)[h][k]
__device__ float    g_f1[HEADS * NN];        // * log2e (exact fp32 path)
__device__ float    g_f2[HEADS * NN];        // * log2e
__device__ float2   g_AC[HEADS * NN];        // (A_i, C_i), scaled by 2^12
__device__ float2   g_BD[HEADS * NN];        // (B_j, D_j), j perm16
__device__ float    g_f2max[HEADS];
__device__ unsigned g_mask[NN * MWORDS];

// ---------------- helpers ----------------
__device__ __forceinline__ ull mul2(ull a, ull b) {
    ull d; asm("mul.rn.f32x2 %0, %1, %2;" : "=l"(d) : "l"(a), "l"(b));
    return d;
}
__device__ __forceinline__ ull pack2f(float lo, float hi) {
    ull d; asm("mov.b64 %0, {%1, %2};" : "=l"(d) : "f"(lo), "f"(hi));
    return d;
}
__device__ __forceinline__ float2 unpack2(ull v) {
    float2 f; asm("mov.b64 {%0, %1}, %2;" : "=f"(f.x), "=f"(f.y) : "l"(v));
    return f;
}
__device__ __forceinline__ unsigned tf32r(float x) {
    unsigned r; asm("cvt.rna.tf32.f32 %0, %1;" : "=r"(r) : "f"(x));
    return r;
}
__device__ __forceinline__ float ex2f(float x) {
    float r; asm("ex2.approx.f32 %0, %1;" : "=f"(r) : "f"(x));
    return r;
}
__device__ __forceinline__ unsigned pack16(float hi, float lo) {
    unsigned r;
    asm("cvt.rn.f16x2.f32 %0, %1, %2;" : "=r"(r) : "f"(hi), "f"(lo));
    return r;
}
__device__ __forceinline__ float maxmul(ull ac, ull bd) {
    float2 f = unpack2(mul2(ac, bd));
    return fmaxf(f.x, f.y);
}
__device__ __forceinline__ void mma_f16(float c[4], unsigned a0, unsigned a1,
                                        unsigned a2, unsigned a3,
                                        unsigned b0, unsigned b1) {
    asm volatile(
        "mma.sync.aligned.m16n8k16.row.col.f32.f16.f16.f32 "
        "{%0,%1,%2,%3}, {%4,%5,%6,%7}, {%8,%9}, {%0,%1,%2,%3};"
        : "+f"(c[0]), "+f"(c[1]), "+f"(c[2]), "+f"(c[3])
        : "r"(a0), "r"(a1), "r"(a2), "r"(a3), "r"(b0), "r"(b1));
}
__device__ __forceinline__ void mma_tf32(float c[4], unsigned a0, unsigned a1,
                                         unsigned a2, unsigned a3,
                                         unsigned b0, unsigned b1) {
    asm volatile(
        "mma.sync.aligned.m16n8k8.row.col.f32.tf32.tf32.f32 "
        "{%0,%1,%2,%3}, {%4,%5,%6,%7}, {%8,%9}, {%0,%1,%2,%3};"
        : "+f"(c[0]), "+f"(c[1]), "+f"(c[2]), "+f"(c[3])
        : "r"(a0), "r"(a1), "r"(a2), "r"(a3), "r"(b0), "r"(b1));
}
__device__ __forceinline__ void cp16(void* dst, const void* src) {
    unsigned d = (unsigned)__cvta_generic_to_shared(dst);
    asm volatile("cp.async.cg.shared.global [%0], [%1], 16;" :: "r"(d), "l"(src));
}
__device__ __forceinline__ void cp8(void* dst, const void* src) {
    unsigned d = (unsigned)__cvta_generic_to_shared(dst);
    asm volatile("cp.async.ca.shared.global [%0], [%1], 8;" :: "r"(d), "l"(src));
}
__device__ __forceinline__ void cp_commit() { asm volatile("cp.async.commit_group;"); }
template <int N> __device__ __forceinline__ void cp_wait() {
    asm volatile("cp.async.wait_group %0;" :: "n"(N));
}

// ---------------- kernel 1: fused prep (mask | tf32-round | w12) ------------
// blocks [0, 32768): adj -> bitmask (MLP-8)
// blocks [32768, 37120): tf32-round x and W
// blocks [37120, 37152): w12 = (W@a1, W@a2)
__global__ __launch_bounds__(256) void fused_prep_kernel(
    const int* __restrict__ adj, const float* __restrict__ x,
    const float* __restrict__ W, const float* __restrict__ a1,
    const float* __restrict__ a2)
{
    const int b = blockIdx.x, t = threadIdx.x;
    if (b < 32768) {
        const int UN = 8;
        long long w0 = ((long long)b * 8 + (t >> 5)) * UN;
        int lane = t & 31;
        int v[UN];
#pragma unroll
        for (int u = 0; u < UN; ++u) v[u] = adj[(w0 + u) * 32 + lane];
#pragma unroll
        for (int u = 0; u < UN; ++u) {
            unsigned bal = __ballot_sync(0xffffffffu, v[u] > 0);
            if (lane == 0) g_mask[w0 + u] = bal;
        }
    } else if (b < 37120) {
        int i = (b - 32768) * 256 + t;   // float4 index
        float4 v;
        float4* dst;
        if (i < 1048576) { v = ((const float4*)x)[i]; dst = &((float4*)g_xr)[i]; }
        else { v = ((const float4*)W)[i - 1048576]; dst = &((float4*)g_Wr)[i - 1048576]; }
        v.x = __uint_as_float(tf32r(v.x));
        v.y = __uint_as_float(tf32r(v.y));
        v.z = __uint_as_float(tf32r(v.z));
        v.w = __uint_as_float(tf32r(v.w));
        *dst = v;
    } else {
        int idx = b - 37120;             // 0..31
        int h = idx >> 2;
        int k = (idx & 3) * 128 + (t >> 1);
        int dh = (t & 1) * 32;
        const float* wrow = W + h * (DIN * DOUT) + k * 64 + dh;
        const float* a1p = a1 + h * 64 + dh;
        const float* a2p = a2 + h * 64 + dh;
        float s1 = 0.f, s2 = 0.f;
#pragma unroll
        for (int d = 0; d < 32; ++d) {
            float w = wrow[d];
            s1 = fmaf(w, a1p[d], s1);
            s2 = fmaf(w, a2p[d], s2);
        }
        s1 += __shfl_xor_sync(0xffffffffu, s1, 1);
        s2 += __shfl_xor_sync(0xffffffffu, s2, 1);
        if ((t & 1) == 0) g_w12[h * 512 + k] = make_float2(s1, s2);
    }
}

// ---------------- kernel 2: Wh GEMM via tf32 mma, fused fp16/perm16 epilogue
#define XSTR 20
#define WSTR 72
__global__ __launch_bounds__(256, 2) void gemm_wh2_kernel() {
    __shared__ __align__(16) float buf[2 * 128 * XSTR + 2 * 16 * WSTR];
    float* xS = buf;                    // [2][128][20]
    float* wS = buf + 2 * 128 * XSTR;   // [2][16][72]
    __half* Csh = (__half*)buf;         // epilogue overlay [64][136]

    const int h = blockIdx.y, row0 = blockIdx.x * 128, t = threadIdx.x;
    const int lane = t & 31, warp = t >> 5, gid = lane >> 2, tig = lane & 3;
    const int mbase = (warp & 3) * 16, nbase = (warp >> 2) * 64;

    float acc[8][4];
#pragma unroll
    for (int nc = 0; nc < 8; ++nc)
#pragma unroll
        for (int q = 0; q < 4; ++q) acc[nc][q] = 0.f;

    const int sj = t >> 1, sk8 = (t & 1) * 8;
    const int wk = t >> 4, wd = (t & 15) * 4;
#define GSTAGE(it, b) do {                                                    \
        const float* xsrc = &g_xr[(long long)(row0 + sj) * 512 + (it) * 16];  \
        cp16(&xS[(b) * 2560 + sj * XSTR + sk8],     xsrc + sk8);              \
        cp16(&xS[(b) * 2560 + sj * XSTR + sk8 + 4], xsrc + sk8 + 4);          \
        cp16(&wS[(b) * 1152 + wk * WSTR + wd],                                \
             &g_Wr[h * (DIN * DOUT) + ((it) * 16 + wk) * 64 + wd]);           \
    } while (0)

    GSTAGE(0, 0); cp_commit();

    for (int it = 0; it < 32; ++it) {
        const int cur = it & 1;
        cp_wait<0>();
        __syncthreads();
        if (it + 1 < 32) GSTAGE(it + 1, cur ^ 1);
        cp_commit();
        const float* xb = xS + cur * 2560;
        const float* wb = wS + cur * 1152;
#pragma unroll
        for (int k8 = 0; k8 < 2; ++k8) {
            const int k0 = k8 * 8;
            const unsigned a0 = __float_as_uint(wb[(k0 + tig) * WSTR + mbase + gid]);
            const unsigned a1 = __float_as_uint(wb[(k0 + tig) * WSTR + mbase + gid + 8]);
            const unsigned a2 = __float_as_uint(wb[(k0 + tig + 4) * WSTR + mbase + gid]);
            const unsigned a3 = __float_as_uint(wb[(k0 + tig + 4) * WSTR + mbase + gid + 8]);
#pragma unroll
            for (int nc = 0; nc < 8; ++nc) {
                const int j = nbase + nc * 8 + gid;
                const unsigned b0 = __float_as_uint(xb[j * XSTR + k0 + tig]);
                const unsigned b1 = __float_as_uint(xb[j * XSTR + k0 + tig + 4]);
                mma_tf32(acc[nc], a0, a1, a2, a3, b0, b1);
            }
        }
    }
    __syncthreads();

#pragma unroll
    for (int nc = 0; nc < 8; ++nc) {
        const int j = nbase + nc * 8 + tig * 2;
        *(__half2*)&Csh[(mbase + gid) * 136 + j] =
            __floats2half2_rn(acc[nc][0], acc[nc][1]);
        *(__half2*)&Csh[(mbase + gid + 8) * 136 + j] =
            __floats2half2_rn(acc[nc][2], acc[nc][3]);
    }
    __syncthreads();

#pragma unroll
    for (int s = 0; s < 4; ++s) {
        int id = t + s * 256;
        int d = id >> 4, c8 = id & 15;
        __half hbuf[8];
#pragma unroll
        for (int e = 0; e < 8; ++e) {
            int p = c8 * 8 + e;
            int pl = p & 15;
            int u = ((pl >> 2) & 3) * 2 + ((pl >> 1) & 1) * 8 + (pl & 1);
            hbuf[e] = Csh[d * 136 + (p & ~15) + u];
        }
        *(uint4*)&g_WhH[((long long)(h * 64 + d)) * NN + row0 + c8 * 8] =
            *(uint4*)hbuf;
    }
}

// ---------------- kernel 2c: f1/f2 = x @ w12 (exact fp32 path) --------------
__global__ __launch_bounds__(256) void f1f2_kernel(const float* __restrict__ x) {
    __shared__ float w1s[8 * 512], w2s[8 * 512];
    const int t = threadIdx.x, lane = t & 31, warp = t >> 5;
    for (int i = t; i < 8 * 512; i += 256) {
        float2 v = g_w12[i];
        w1s[i] = v.x; w2s[i] = v.y;
    }
    __syncthreads();
    for (int it = 0; it < 4; ++it) {
        const int node = blockIdx.x * 32 + warp * 4 + it;
        float4 xv[4];
#pragma unroll
        for (int q = 0; q < 4; ++q)
            xv[q] = ((const float4*)x)[(long long)node * 128 + lane + 32 * q];
        float f1r[8], f2r[8];
#pragma unroll
        for (int h = 0; h < 8; ++h) {
            float s1 = 0.f, s2 = 0.f;
#pragma unroll
            for (int q = 0; q < 4; ++q) {
                float4 w1 = *(const float4*)&w1s[h * 512 + 4 * lane + 128 * q];
                float4 w2 = *(const float4*)&w2s[h * 512 + 4 * lane + 128 * q];
                s1 = fmaf(xv[q].x, w1.x, s1); s1 = fmaf(xv[q].y, w1.y, s1);
                s1 = fmaf(xv[q].z, w1.z, s1); s1 = fmaf(xv[q].w, w1.w, s1);
                s2 = fmaf(xv[q].x, w2.x, s2); s2 = fmaf(xv[q].y, w2.y, s2);
                s2 = fmaf(xv[q].z, w2.z, s2); s2 = fmaf(xv[q].w, w2.w, s2);
            }
            f1r[h] = s1; f2r[h] = s2;
        }
#pragma unroll
        for (int s = 16; s; s >>= 1)
#pragma unroll
            for (int h = 0; h < 8; ++h) {
                f1r[h] += __shfl_xor_sync(0xffffffffu, f1r[h], s);
                f2r[h] += __shfl_xor_sync(0xffffffffu, f2r[h], s);
            }
        if (lane == 0)
#pragma unroll
            for (int h = 0; h < 8; ++h) {
                g_f1[h * NN + node] = f1r[h] * L2E;
                g_f2[h * NN + node] = f2r[h] * L2E;
            }
    }
}

// ---------------- kernel 2d: per-head max of f2 ----------------
__global__ __launch_bounds__(256) void f2max_kernel() {
    __shared__ float red[8];
    int h = blockIdx.x;
    float m = -3.4e38f;
    for (int i = threadIdx.x; i < NN; i += 256)
        m = fmaxf(m, g_f2[h * NN + i]);
#pragma unroll
    for (int s = 16; s; s >>= 1)
        m = fmaxf(m, __shfl_xor_sync(0xffffffffu, m, s));
    if ((threadIdx.x & 31) == 0) red[threadIdx.x >> 5] = m;
    __syncthreads();
    if (threadIdx.x < 8) {
        m = red[threadIdx.x];
#pragma unroll
        for (int s = 4; s; s >>= 1)
            m = fmaxf(m, __shfl_xor_sync(0x000000ffu, m, s));
        if (threadIdx.x == 0) g_f2max[h] = m;
    }
}

// ---------------- kernel 2e: precompute A,C (2^12-scaled) and B,D (perm16) --
__global__ __launch_bounds__(256) void prep_kernel() {
    int h = blockIdx.y;
    int i = blockIdx.x * 256 + threadIdx.x;
    float f2m = g_f2max[h];
    float f1 = g_f1[h * NN + i];
    float e = f1 + f2m;
    float m = fmaxf(e, 0.2f * e);
    g_AC[h * NN + i] =
        make_float2(ex2f(e - m + PSCALE), ex2f(0.2f * e - m + PSCALE));
    float dd = g_f2[h * NN + i] - f2m;
    int u = i & 15;
    int pos = ((u & 7) >> 1) * 4 + ((u >> 3) & 1) * 2 + (u & 1);
    g_BD[h * NN + (i & ~15) + pos] = make_float2(ex2f(dd), ex2f(0.2f * dd));
}

// ---------------- kernel 3: attention (fp16 k16 mma, no exp in loop) --------
__global__ __launch_bounds__(256, 2) void attn_kernel(float* __restrict__ out) {
    __shared__ __align__(16) __half   WhS[3][64 * 72];
    __shared__ __align__(16) float2   bdS[3][64];
    __shared__ __align__(16) unsigned maskS[3][512];

    const int h = blockIdx.y, row0 = blockIdx.x * 256, t = threadIdx.x;
    const int lane = t & 31, warp = t >> 5, gid = lane >> 2, tig = lane & 3;
    const int rbase = warp * 32 + gid;

    ull ACp[4];
#pragma unroll
    for (int r = 0; r < 4; ++r) {
        float2 ac = g_AC[h * NN + row0 + rbase + r * 8];
        ACp[r] = pack2f(ac.x, ac.y);
    }

    float acc[2][8][4];
    float accL[2][4];
#pragma unroll
    for (int b = 0; b < 2; ++b) {
#pragma unroll
        for (int nc = 0; nc < 8; ++nc)
#pragma unroll
            for (int q = 0; q < 4; ++q) acc[b][nc][q] = 0.f;
#pragma unroll
        for (int q = 0; q < 4; ++q) accL[b][q] = 0.f;
    }

    const int sd = t >> 2, sc = t & 3;
#define STAGE(jt, b) do {                                                     \
        long long js = (long long)(jt) * 64;                                  \
        const __half* srow = &g_WhH[((long long)(h * 64 + sd)) * NN + js];    \
        cp16(&WhS[b][sd * 72 + sc * 16],     srow + sc * 16);                 \
        cp16(&WhS[b][sd * 72 + sc * 16 + 8], srow + sc * 16 + 8);             \
        cp8(&maskS[b][t * 2],                                                 \
            &g_mask[(long long)(row0 + t) * MWORDS + (jt) * 2]);              \
        if (t < 32) cp16(&bdS[b][t * 2], &g_BD[h * NN + js + t * 2]);         \
    } while (0)

// one tile body; CUR/NB are compile-time constants
#define ABODY(JT, CUR, NB) do {                                               \
        cp_wait<1>();                                                         \
        __syncthreads();                                                      \
        if ((JT) + 2 < 128) STAGE((JT) + 2, NB);                              \
        cp_commit();                                                          \
        unsigned mw0[4], mw1[4];                                              \
        _Pragma("unroll")                                                     \
        for (int r = 0; r < 4; ++r) {                                         \
            mw0[r] = maskS[CUR][(rbase + r * 8) * 2];                         \
            mw1[r] = maskS[CUR][(rbase + r * 8) * 2 + 1];                     \
        }                                                                     \
        const __half* whb = &WhS[CUR][gid * 72 + tig * 4];                    \
        const float2* bdb = &bdS[CUR][tig * 4];                               \
        _Pragma("unroll")                                                     \
        for (int ks = 0; ks < 4; ++ks) {                                      \
            const ulonglong2 bdv = *(const ulonglong2*)(bdb + ks * 16);       \
            const ulonglong2 bdw = *(const ulonglong2*)(bdb + ks * 16 + 2);   \
            const int sh = ((ks & 1) << 4) + 2 * tig;                         \
            unsigned fa[4][2];                                                \
            _Pragma("unroll")                                                 \
            for (int r = 0; r < 4; ++r) {                                     \
                const unsigned xb = ((ks < 2) ? mw0[r] : mw1[r]) >> sh;       \
                float p0 = maxmul(ACp[r], bdv.x);                             \
                float p1 = maxmul(ACp[r], bdv.y);                             \
                float p2 = maxmul(ACp[r], bdw.x);                             \
                float p3 = maxmul(ACp[r], bdw.y);                             \
                if (!(xb & 1u))     p0 = 0.f;                                 \
                if (!(xb & 2u))     p1 = 0.f;                                 \
                if (!(xb & 0x100u)) p2 = 0.f;                                 \
                if (!(xb & 0x200u)) p3 = 0.f;                                 \
                fa[r][0] = pack16(p1, p0);                                    \
                fa[r][1] = pack16(p3, p2);                                    \
            }                                                                 \
            _Pragma("unroll")                                                 \
            for (int nc = 0; nc < 8; ++nc) {                                  \
                const uint2 bb = *(const uint2*)(whb + nc * 576 + ks * 16);   \
                mma_f16(acc[0][nc], fa[0][0], fa[1][0], fa[0][1], fa[1][1],   \
                        bb.x, bb.y);                                          \
                mma_f16(acc[1][nc], fa[2][0], fa[3][0], fa[2][1], fa[3][1],   \
                        bb.x, bb.y);                                          \
            }                                                                 \
            mma_f16(accL[0], fa[0][0], fa[1][0], fa[0][1], fa[1][1],          \
                    ONE2, ONE2);                                              \
            mma_f16(accL[1], fa[2][0], fa[3][0], fa[2][1], fa[3][1],          \
                    ONE2, ONE2);                                              \
        }                                                                     \
    } while (0)

    STAGE(0, 0); cp_commit();
    STAGE(1, 1); cp_commit();

    for (int j3 = 0; j3 < 126; j3 += 3) {
        ABODY(j3,     0, 2);
        ABODY(j3 + 1, 1, 0);
        ABODY(j3 + 2, 2, 1);
    }
    ABODY(126, 0, 2);
    ABODY(127, 1, 0);

#pragma unroll
    for (int b = 0; b < 2; ++b) {
        const float invLo = 1.0f / accL[b][0];
        const float invHi = 1.0f / accL[b][2];
        const long long ga = row0 + rbase + b * 16;
        const long long gb = ga + 8;
#pragma unroll
        for (int nc = 0; nc < 8; ++nc) {
            const int col = h * 64 + nc * 8 + tig * 2;
            ((float2*)out)[(ga * 512 + col) >> 1] =
                make_float2(acc[b][nc][0] * invLo, acc[b][nc][1] * invLo);
            ((float2*)out)[(gb * 512 + col) >> 1] =
                make_float2(acc[b][nc][2] * invHi, acc[b][nc][3] * invHi);
        }
    }
}

// ---------------- launch ----------------
extern "C" void kernel_launch(void* const* d_in, const int* in_sizes, int n_in,
                              void* d_out, int out_size) {
    const float* x   = (const float*)d_in[0];
    const int*   adj = (const int*)d_in[1];
    const float* W   = (const float*)d_in[2];
    const float* a1  = (const float*)d_in[3];
    const float* a2  = (const float*)d_in[4];
    float* out = (float*)d_out;

    fused_prep_kernel<<<37152, 256>>>(adj, x, W, a1, a2);
    gemm_wh2_kernel<<<dim3(NN / 128, HEADS), 256>>>();
    f1f2_kernel<<<NN / 32, 256>>>(x);
    f2max_kernel<<<HEADS, 256>>>();
    prep_kernel<<<dim3(NN / 256, HEADS), 256>>>();
    attn_kernel<<<dim3(NN / 256, HEADS), 256>>>(out);
}

// round 13
// speedup vs baseline: 1.0580x; 1.0580x over previous
#include <cuda_runtime.h>
#include <cuda_fp16.h>
#include <cstdint>

#define NN 8192
#define DIN 512
#define DOUT 64
#define HEADS 8
#define MWORDS 256
#define L2E 1.44269504088896f
#define ONE2 0x3C003C00u
#define PSCALE 12.0f   // p scaled by 2^12: lifts fp16 operands out of denormal range

typedef unsigned long long ull;

__device__ __half   g_WhH[HEADS * 64 * NN];  // [h][d][j perm16] fp16
__device__ float    g_xr[NN * DIN];          // tf32-rounded x
__device__ float    g_Wr[HEADS * DIN * DOUT];// tf32-rounded W
__device__ float2   g_w12[HEADS * DIN];      // (W@a1, W@a2)[h][k]
__device__ float    g_f1[HEADS * NN];        // * log2e (exact fp32 path)
__device__ float    g_f2[HEADS * NN];        // * log2e
__device__ float2   g_AC[HEADS * NN];        // (A_i, C_i), scaled by 2^12
__device__ float2   g_BD[HEADS * NN];        // (B_j, D_j), j perm16
__device__ float    g_f2max[HEADS];
__device__ unsigned g_mask[NN * MWORDS];

// ---------------- helpers ----------------
__device__ __forceinline__ ull mul2(ull a, ull b) {
    ull d; asm("mul.rn.f32x2 %0, %1, %2;" : "=l"(d) : "l"(a), "l"(b));
    return d;
}
__device__ __forceinline__ ull pack2f(float lo, float hi) {
    ull d; asm("mov.b64 %0, {%1, %2};" : "=l"(d) : "f"(lo), "f"(hi));
    return d;
}
__device__ __forceinline__ float2 unpack2(ull v) {
    float2 f; asm("mov.b64 {%0, %1}, %2;" : "=f"(f.x), "=f"(f.y) : "l"(v));
    return f;
}
__device__ __forceinline__ unsigned tf32r(float x) {
    unsigned r; asm("cvt.rna.tf32.f32 %0, %1;" : "=r"(r) : "f"(x));
    return r;
}
__device__ __forceinline__ float ex2f(float x) {
    float r; asm("ex2.approx.f32 %0, %1;" : "=f"(r) : "f"(x));
    return r;
}
__device__ __forceinline__ unsigned pack16(float hi, float lo) {
    unsigned r;
    asm("cvt.rn.f16x2.f32 %0, %1, %2;" : "=r"(r) : "f"(hi), "f"(lo));
    return r;
}
__device__ __forceinline__ float maxmul(ull ac, ull bd) {
    float2 f = unpack2(mul2(ac, bd));
    return fmaxf(f.x, f.y);
}
__device__ __forceinline__ void mma_f16(float c[4], unsigned a0, unsigned a1,
                                        unsigned a2, unsigned a3,
                                        unsigned b0, unsigned b1) {
    asm volatile(
        "mma.sync.aligned.m16n8k16.row.col.f32.f16.f16.f32 "
        "{%0,%1,%2,%3}, {%4,%5,%6,%7}, {%8,%9}, {%0,%1,%2,%3};"
        : "+f"(c[0]), "+f"(c[1]), "+f"(c[2]), "+f"(c[3])
        : "r"(a0), "r"(a1), "r"(a2), "r"(a3), "r"(b0), "r"(b1));
}
__device__ __forceinline__ void mma_tf32(float c[4], unsigned a0, unsigned a1,
                                         unsigned a2, unsigned a3,
                                         unsigned b0, unsigned b1) {
    asm volatile(
        "mma.sync.aligned.m16n8k8.row.col.f32.tf32.tf32.f32 "
        "{%0,%1,%2,%3}, {%4,%5,%6,%7}, {%8,%9}, {%0,%1,%2,%3};"
        : "+f"(c[0]), "+f"(c[1]), "+f"(c[2]), "+f"(c[3])
        : "r"(a0), "r"(a1), "r"(a2), "r"(a3), "r"(b0), "r"(b1));
}
__device__ __forceinline__ void cp16(void* dst, const void* src) {
    unsigned d = (unsigned)__cvta_generic_to_shared(dst);
    asm volatile("cp.async.cg.shared.global [%0], [%1], 16;" :: "r"(d), "l"(src));
}
__device__ __forceinline__ void cp8(void* dst, const void* src) {
    unsigned d = (unsigned)__cvta_generic_to_shared(dst);
    asm volatile("cp.async.ca.shared.global [%0], [%1], 8;" :: "r"(d), "l"(src));
}
__device__ __forceinline__ void cp_commit() { asm volatile("cp.async.commit_group;"); }
template <int N> __device__ __forceinline__ void cp_wait() {
    asm volatile("cp.async.wait_group %0;" :: "n"(N));
}

// ---------------- kernel 1: fused prep (mask | tf32-round | w12) ------------
__global__ __launch_bounds__(256) void fused_prep_kernel(
    const int* __restrict__ adj, const float* __restrict__ x,
    const float* __restrict__ W, const float* __restrict__ a1,
    const float* __restrict__ a2)
{
    const int b = blockIdx.x, t = threadIdx.x;
    if (b < 32768) {
        const int UN = 8;
        long long w0 = ((long long)b * 8 + (t >> 5)) * UN;
        int lane = t & 31;
        int v[UN];
#pragma unroll
        for (int u = 0; u < UN; ++u) v[u] = adj[(w0 + u) * 32 + lane];
#pragma unroll
        for (int u = 0; u < UN; ++u) {
            unsigned bal = __ballot_sync(0xffffffffu, v[u] > 0);
            if (lane == 0) g_mask[w0 + u] = bal;
        }
    } else if (b < 37120) {
        int i = (b - 32768) * 256 + t;   // float4 index
        float4 v;
        float4* dst;
        if (i < 1048576) { v = ((const float4*)x)[i]; dst = &((float4*)g_xr)[i]; }
        else { v = ((const float4*)W)[i - 1048576]; dst = &((float4*)g_Wr)[i - 1048576]; }
        v.x = __uint_as_float(tf32r(v.x));
        v.y = __uint_as_float(tf32r(v.y));
        v.z = __uint_as_float(tf32r(v.z));
        v.w = __uint_as_float(tf32r(v.w));
        *dst = v;
    } else {
        int idx = b - 37120;             // 0..31
        int h = idx >> 2;
        int k = (idx & 3) * 128 + (t >> 1);
        int dh = (t & 1) * 32;
        const float* wrow = W + h * (DIN * DOUT) + k * 64 + dh;
        const float* a1p = a1 + h * 64 + dh;
        const float* a2p = a2 + h * 64 + dh;
        float s1 = 0.f, s2 = 0.f;
#pragma unroll
        for (int d = 0; d < 32; ++d) {
            float w = wrow[d];
            s1 = fmaf(w, a1p[d], s1);
            s2 = fmaf(w, a2p[d], s2);
        }
        s1 += __shfl_xor_sync(0xffffffffu, s1, 1);
        s2 += __shfl_xor_sync(0xffffffffu, s2, 1);
        if ((t & 1) == 0) g_w12[h * 512 + k] = make_float2(s1, s2);
    }
}

// ---------------- kernel 2: Wh GEMM via tf32 mma, fused fp16/perm16 epilogue
#define XSTR 20
#define WSTR 72
__global__ __launch_bounds__(256, 2) void gemm_wh2_kernel() {
    __shared__ __align__(16) float buf[2 * 128 * XSTR + 2 * 16 * WSTR];
    float* xS = buf;                    // [2][128][20]
    float* wS = buf + 2 * 128 * XSTR;   // [2][16][72]
    __half* Csh = (__half*)buf;         // epilogue overlay [64][136]

    const int h = blockIdx.y, row0 = blockIdx.x * 128, t = threadIdx.x;
    const int lane = t & 31, warp = t >> 5, gid = lane >> 2, tig = lane & 3;
    const int mbase = (warp & 3) * 16, nbase = (warp >> 2) * 64;

    float acc[8][4];
#pragma unroll
    for (int nc = 0; nc < 8; ++nc)
#pragma unroll
        for (int q = 0; q < 4; ++q) acc[nc][q] = 0.f;

    const int sj = t >> 1, sk8 = (t & 1) * 8;
    const int wk = t >> 4, wd = (t & 15) * 4;
#define GSTAGE(it, b) do {                                                    \
        const float* xsrc = &g_xr[(long long)(row0 + sj) * 512 + (it) * 16];  \
        cp16(&xS[(b) * 2560 + sj * XSTR + sk8],     xsrc + sk8);              \
        cp16(&xS[(b) * 2560 + sj * XSTR + sk8 + 4], xsrc + sk8 + 4);          \
        cp16(&wS[(b) * 1152 + wk * WSTR + wd],                                \
             &g_Wr[h * (DIN * DOUT) + ((it) * 16 + wk) * 64 + wd]);           \
    } while (0)

    GSTAGE(0, 0); cp_commit();

    for (int it = 0; it < 32; ++it) {
        const int cur = it & 1;
        cp_wait<0>();
        __syncthreads();
        if (it + 1 < 32) GSTAGE(it + 1, cur ^ 1);
        cp_commit();
        const float* xb = xS + cur * 2560;
        const float* wb = wS + cur * 1152;
#pragma unroll
        for (int k8 = 0; k8 < 2; ++k8) {
            const int k0 = k8 * 8;
            const unsigned a0 = __float_as_uint(wb[(k0 + tig) * WSTR + mbase + gid]);
            const unsigned a1 = __float_as_uint(wb[(k0 + tig) * WSTR + mbase + gid + 8]);
            const unsigned a2 = __float_as_uint(wb[(k0 + tig + 4) * WSTR + mbase + gid]);
            const unsigned a3 = __float_as_uint(wb[(k0 + tig + 4) * WSTR + mbase + gid + 8]);
#pragma unroll
            for (int nc = 0; nc < 8; ++nc) {
                const int j = nbase + nc * 8 + gid;
                const unsigned b0 = __float_as_uint(xb[j * XSTR + k0 + tig]);
                const unsigned b1 = __float_as_uint(xb[j * XSTR + k0 + tig + 4]);
                mma_tf32(acc[nc], a0, a1, a2, a3, b0, b1);
            }
        }
    }
    __syncthreads();

#pragma unroll
    for (int nc = 0; nc < 8; ++nc) {
        const int j = nbase + nc * 8 + tig * 2;
        *(__half2*)&Csh[(mbase + gid) * 136 + j] =
            __floats2half2_rn(acc[nc][0], acc[nc][1]);
        *(__half2*)&Csh[(mbase + gid + 8) * 136 + j] =
            __floats2half2_rn(acc[nc][2], acc[nc][3]);
    }
    __syncthreads();

#pragma unroll
    for (int s = 0; s < 4; ++s) {
        int id = t + s * 256;
        int d = id >> 4, c8 = id & 15;
        __half hbuf[8];
#pragma unroll
        for (int e = 0; e < 8; ++e) {
            int p = c8 * 8 + e;
            int pl = p & 15;
            int u = ((pl >> 2) & 3) * 2 + ((pl >> 1) & 1) * 8 + (pl & 1);
            hbuf[e] = Csh[d * 136 + (p & ~15) + u];
        }
        *(uint4*)&g_WhH[((long long)(h * 64 + d)) * NN + row0 + c8 * 8] =
            *(uint4*)hbuf;
    }
}

// ---------------- kernel 2c: f1/f2 = x @ w12 (exact fp32 path) --------------
__global__ __launch_bounds__(256) void f1f2_kernel(const float* __restrict__ x) {
    __shared__ float w1s[8 * 512], w2s[8 * 512];
    const int t = threadIdx.x, lane = t & 31, warp = t >> 5;
    for (int i = t; i < 8 * 512; i += 256) {
        float2 v = g_w12[i];
        w1s[i] = v.x; w2s[i] = v.y;
    }
    __syncthreads();
    for (int it = 0; it < 4; ++it) {
        const int node = blockIdx.x * 32 + warp * 4 + it;
        float4 xv[4];
#pragma unroll
        for (int q = 0; q < 4; ++q)
            xv[q] = ((const float4*)x)[(long long)node * 128 + lane + 32 * q];
        float f1r[8], f2r[8];
#pragma unroll
        for (int h = 0; h < 8; ++h) {
            float s1 = 0.f, s2 = 0.f;
#pragma unroll
            for (int q = 0; q < 4; ++q) {
                float4 w1 = *(const float4*)&w1s[h * 512 + 4 * lane + 128 * q];
                float4 w2 = *(const float4*)&w2s[h * 512 + 4 * lane + 128 * q];
                s1 = fmaf(xv[q].x, w1.x, s1); s1 = fmaf(xv[q].y, w1.y, s1);
                s1 = fmaf(xv[q].z, w1.z, s1); s1 = fmaf(xv[q].w, w1.w, s1);
                s2 = fmaf(xv[q].x, w2.x, s2); s2 = fmaf(xv[q].y, w2.y, s2);
                s2 = fmaf(xv[q].z, w2.z, s2); s2 = fmaf(xv[q].w, w2.w, s2);
            }
            f1r[h] = s1; f2r[h] = s2;
        }
#pragma unroll
        for (int s = 16; s; s >>= 1)
#pragma unroll
            for (int h = 0; h < 8; ++h) {
                f1r[h] += __shfl_xor_sync(0xffffffffu, f1r[h], s);
                f2r[h] += __shfl_xor_sync(0xffffffffu, f2r[h], s);
            }
        if (lane == 0)
#pragma unroll
            for (int h = 0; h < 8; ++h) {
                g_f1[h * NN + node] = f1r[h] * L2E;
                g_f2[h * NN + node] = f2r[h] * L2E;
            }
    }
}

// ---------------- kernel 2d: per-head max of f2 (1024 threads) --------------
__global__ __launch_bounds__(1024) void f2max_kernel() {
    __shared__ float red[32];
    int h = blockIdx.x;
    float m = -3.4e38f;
    for (int i = threadIdx.x; i < NN; i += 1024)
        m = fmaxf(m, g_f2[h * NN + i]);
#pragma unroll
    for (int s = 16; s; s >>= 1)
        m = fmaxf(m, __shfl_xor_sync(0xffffffffu, m, s));
    if ((threadIdx.x & 31) == 0) red[threadIdx.x >> 5] = m;
    __syncthreads();
    if (threadIdx.x < 32) {
        m = red[threadIdx.x];
#pragma unroll
        for (int s = 16; s; s >>= 1)
            m = fmaxf(m, __shfl_xor_sync(0xffffffffu, m, s));
        if (threadIdx.x == 0) g_f2max[h] = m;
    }
}

// ---------------- kernel 2e: precompute A,C (2^12-scaled) and B,D (perm16) --
__global__ __launch_bounds__(256) void prep_kernel() {
    int h = blockIdx.y;
    int i = blockIdx.x * 256 + threadIdx.x;
    float f2m = g_f2max[h];
    float f1 = g_f1[h * NN + i];
    float e = f1 + f2m;
    float m = fmaxf(e, 0.2f * e);
    g_AC[h * NN + i] =
        make_float2(ex2f(e - m + PSCALE), ex2f(0.2f * e - m + PSCALE));
    float dd = g_f2[h * NN + i] - f2m;
    int u = i & 15;
    int pos = ((u & 7) >> 1) * 4 + ((u >> 3) & 1) * 2 + (u & 1);
    g_BD[h * NN + (i & ~15) + pos] = make_float2(ex2f(dd), ex2f(0.2f * dd));
}

// ---------------- kernel 3: attention (fp16 k16 mma, no exp in loop) --------
// r11 structure (rolled loop, dynamic cur) — measured-best configuration.
__global__ __launch_bounds__(256, 2) void attn_kernel(float* __restrict__ out) {
    __shared__ __align__(16) __half   WhS[3][64 * 72];
    __shared__ __align__(16) float2   bdS[3][64];
    __shared__ __align__(16) unsigned maskS[3][512];

    const int h = blockIdx.y, row0 = blockIdx.x * 256, t = threadIdx.x;
    const int lane = t & 31, warp = t >> 5, gid = lane >> 2, tig = lane & 3;
    const int rbase = warp * 32 + gid;

    ull ACp[4];
#pragma unroll
    for (int r = 0; r < 4; ++r) {
        float2 ac = g_AC[h * NN + row0 + rbase + r * 8];
        ACp[r] = pack2f(ac.x, ac.y);
    }

    float acc[2][8][4];
    float accL[2][4];
#pragma unroll
    for (int b = 0; b < 2; ++b) {
#pragma unroll
        for (int nc = 0; nc < 8; ++nc)
#pragma unroll
            for (int q = 0; q < 4; ++q) acc[b][nc][q] = 0.f;
#pragma unroll
        for (int q = 0; q < 4; ++q) accL[b][q] = 0.f;
    }

    const int sd = t >> 2, sc = t & 3;
#define STAGE(jt, b) do {                                                     \
        long long js = (long long)(jt) * 64;                                  \
        const __half* srow = &g_WhH[((long long)(h * 64 + sd)) * NN + js];    \
        cp16(&WhS[b][sd * 72 + sc * 16],     srow + sc * 16);                 \
        cp16(&WhS[b][sd * 72 + sc * 16 + 8], srow + sc * 16 + 8);             \
        cp8(&maskS[b][t * 2],                                                 \
            &g_mask[(long long)(row0 + t) * MWORDS + (jt) * 2]);              \
        if (t < 32) cp16(&bdS[b][t * 2], &g_BD[h * NN + js + t * 2]);         \
    } while (0)

    STAGE(0, 0); cp_commit();
    STAGE(1, 1); cp_commit();

    int cur = 0;
    for (int jt = 0; jt < 128; ++jt) {
        cp_wait<1>();
        __syncthreads();

        unsigned mw0[4], mw1[4];
#pragma unroll
        for (int r = 0; r < 4; ++r) {
            mw0[r] = maskS[cur][(rbase + r * 8) * 2];
            mw1[r] = maskS[cur][(rbase + r * 8) * 2 + 1];
        }
        const __half* whb = &WhS[cur][gid * 72 + tig * 4];
        const float2* bdb = &bdS[cur][tig * 4];

#pragma unroll
        for (int ks = 0; ks < 4; ++ks) {
            const ulonglong2 bdv = *(const ulonglong2*)(bdb + ks * 16);
            const ulonglong2 bdw = *(const ulonglong2*)(bdb + ks * 16 + 2);
            const int sh = ((ks & 1) << 4) + 2 * tig;
            unsigned fa[4][2];
#pragma unroll
            for (int r = 0; r < 4; ++r) {
                const unsigned x = ((ks < 2) ? mw0[r] : mw1[r]) >> sh;
                float p0 = maxmul(ACp[r], bdv.x);
                float p1 = maxmul(ACp[r], bdv.y);
                float p2 = maxmul(ACp[r], bdw.x);
                float p3 = maxmul(ACp[r], bdw.y);
                if (!(x & 1u))     p0 = 0.f;
                if (!(x & 2u))     p1 = 0.f;
                if (!(x & 0x100u)) p2 = 0.f;
                if (!(x & 0x200u)) p3 = 0.f;
                fa[r][0] = pack16(p1, p0);
                fa[r][1] = pack16(p3, p2);
            }
#pragma unroll
            for (int nc = 0; nc < 8; ++nc) {
                const uint2 bb = *(const uint2*)(whb + nc * 576 + ks * 16);
                mma_f16(acc[0][nc], fa[0][0], fa[1][0], fa[0][1], fa[1][1],
                        bb.x, bb.y);
                mma_f16(acc[1][nc], fa[2][0], fa[3][0], fa[2][1], fa[3][1],
                        bb.x, bb.y);
            }
            mma_f16(accL[0], fa[0][0], fa[1][0], fa[0][1], fa[1][1], ONE2, ONE2);
            mma_f16(accL[1], fa[2][0], fa[3][0], fa[2][1], fa[3][1], ONE2, ONE2);
        }

        if (jt < 126) {
            int nb = cur >= 1 ? cur - 1 : cur + 2;   // (jt+2)%3
            STAGE(jt + 2, nb);
        }
        cp_commit();
        cur = (cur == 2) ? 0 : cur + 1;
    }

#pragma unroll
    for (int b = 0; b < 2; ++b) {
        const float invLo = 1.0f / accL[b][0];
        const float invHi = 1.0f / accL[b][2];
        const long long ga = row0 + rbase + b * 16;
        const long long gb = ga + 8;
#pragma unroll
        for (int nc = 0; nc < 8; ++nc) {
            const int col = h * 64 + nc * 8 + tig * 2;
            ((float2*)out)[(ga * 512 + col) >> 1] =
                make_float2(acc[b][nc][0] * invLo, acc[b][nc][1] * invLo);
            ((float2*)out)[(gb * 512 + col) >> 1] =
                make_float2(acc[b][nc][2] * invHi, acc[b][nc][3] * invHi);
        }
    }
}

// ---------------- launch ----------------
extern "C" void kernel_launch(void* const* d_in, const int* in_sizes, int n_in,
                              void* d_out, int out_size) {
    const float* x   = (const float*)d_in[0];
    const int*   adj = (const int*)d_in[1];
    const float* W   = (const float*)d_in[2];
    const float* a1  = (const float*)d_in[3];
    const float* a2  = (const float*)d_in[4];
    float* out = (float*)d_out;

    fused_prep_kernel<<<37152, 256>>>(adj, x, W, a1, a2);
    gemm_wh2_kernel<<<dim3(NN / 128, HEADS), 256>>>();
    f1f2_kernel<<<NN / 32, 256>>>(x);
    f2max_kernel<<<HEADS, 1024>>>();
    prep_kernel<<<dim3(NN / 256, HEADS), 256>>>();
    attn_kernel<<<dim3(NN / 256, HEADS), 256>>>(out);
}

// round 14
// speedup vs baseline: 1.0645x; 1.0062x over previous
#include <cuda_runtime.h>
#include <cuda_fp16.h>
#include <cstdint>

#define NN 8192
#define DIN 512
#define DOUT 64
#define HEADS 8
#define MWORDS 256
#define L2E 1.44269504088896f
#define ONE2 0x3C003C00u
#define PSCALE 12.0f   // p scaled by 2^12: lifts fp16 operands out of denormal range

typedef unsigned long long ull;

__device__ __half   g_WhH[HEADS * 64 * NN];  // [h][d][j perm16] fp16
__device__ float    g_xr[NN * DIN];          // tf32-rounded x
__device__ float    g_Wr[HEADS * DIN * DOUT];// tf32-rounded W
__device__ float2   g_w12[HEADS * DIN];      // (W@a1, W@a2)[h][k]
__device__ float    g_f1[HEADS * NN];        // * log2e (exact fp32 path)
__device__ float    g_f2[HEADS * NN];        // * log2e
__device__ float2   g_AC[HEADS * NN];        // (A_i, C_i), scaled by 2^12
__device__ float2   g_BD[HEADS * NN];        // (B_j, D_j), j perm16
__device__ unsigned g_f2maxU[HEADS];         // sortable-uint encoded max(f2)
__device__ unsigned g_mask[NN * MWORDS];

// ---------------- helpers ----------------
__device__ __forceinline__ ull mul2(ull a, ull b) {
    ull d; asm("mul.rn.f32x2 %0, %1, %2;" : "=l"(d) : "l"(a), "l"(b));
    return d;
}
__device__ __forceinline__ ull pack2f(float lo, float hi) {
    ull d; asm("mov.b64 %0, {%1, %2};" : "=l"(d) : "f"(lo), "f"(hi));
    return d;
}
__device__ __forceinline__ float2 unpack2(ull v) {
    float2 f; asm("mov.b64 {%0, %1}, %2;" : "=f"(f.x), "=f"(f.y) : "l"(v));
    return f;
}
__device__ __forceinline__ unsigned tf32r(float x) {
    unsigned r; asm("cvt.rna.tf32.f32 %0, %1;" : "=r"(r) : "f"(x));
    return r;
}
__device__ __forceinline__ float ex2f(float x) {
    float r; asm("ex2.approx.f32 %0, %1;" : "=f"(r) : "f"(x));
    return r;
}
__device__ __forceinline__ unsigned pack16(float hi, float lo) {
    unsigned r;
    asm("cvt.rn.f16x2.f32 %0, %1, %2;" : "=r"(r) : "f"(hi), "f"(lo));
    return r;
}
__device__ __forceinline__ float maxmul(ull ac, ull bd) {
    float2 f = unpack2(mul2(ac, bd));
    return fmaxf(f.x, f.y);
}
// order-preserving float <-> uint encoding (max over uints == fmax over floats)
__device__ __forceinline__ unsigned fenc(float f) {
    unsigned b = __float_as_uint(f);
    return (b & 0x80000000u) ? ~b : (b | 0x80000000u);
}
__device__ __forceinline__ float fdec(unsigned u) {
    unsigned b = (u & 0x80000000u) ? (u & 0x7FFFFFFFu) : ~u;
    return __uint_as_float(b);
}
__device__ __forceinline__ void mma_f16(float c[4], unsigned a0, unsigned a1,
                                        unsigned a2, unsigned a3,
                                        unsigned b0, unsigned b1) {
    asm volatile(
        "mma.sync.aligned.m16n8k16.row.col.f32.f16.f16.f32 "
        "{%0,%1,%2,%3}, {%4,%5,%6,%7}, {%8,%9}, {%0,%1,%2,%3};"
        : "+f"(c[0]), "+f"(c[1]), "+f"(c[2]), "+f"(c[3])
        : "r"(a0), "r"(a1), "r"(a2), "r"(a3), "r"(b0), "r"(b1));
}
__device__ __forceinline__ void mma_tf32(float c[4], unsigned a0, unsigned a1,
                                         unsigned a2, unsigned a3,
                                         unsigned b0, unsigned b1) {
    asm volatile(
        "mma.sync.aligned.m16n8k8.row.col.f32.tf32.tf32.f32 "
        "{%0,%1,%2,%3}, {%4,%5,%6,%7}, {%8,%9}, {%0,%1,%2,%3};"
        : "+f"(c[0]), "+f"(c[1]), "+f"(c[2]), "+f"(c[3])
        : "r"(a0), "r"(a1), "r"(a2), "r"(a3), "r"(b0), "r"(b1));
}
__device__ __forceinline__ void cp16(void* dst, const void* src) {
    unsigned d = (unsigned)__cvta_generic_to_shared(dst);
    asm volatile("cp.async.cg.shared.global [%0], [%1], 16;" :: "r"(d), "l"(src));
}
__device__ __forceinline__ void cp8(void* dst, const void* src) {
    unsigned d = (unsigned)__cvta_generic_to_shared(dst);
    asm volatile("cp.async.ca.shared.global [%0], [%1], 8;" :: "r"(d), "l"(src));
}
__device__ __forceinline__ void cp_commit() { asm volatile("cp.async.commit_group;"); }
template <int N> __device__ __forceinline__ void cp_wait() {
    asm volatile("cp.async.wait_group %0;" :: "n"(N));
}

// ---------------- kernel 1: fused prep (mask | tf32-round | w12 | init) -----
__global__ __launch_bounds__(256) void fused_prep_kernel(
    const int* __restrict__ adj, const float* __restrict__ x,
    const float* __restrict__ W, const float* __restrict__ a1,
    const float* __restrict__ a2)
{
    const int b = blockIdx.x, t = threadIdx.x;
    if (b < 32768) {
        const int UN = 8;
        long long w0 = ((long long)b * 8 + (t >> 5)) * UN;
        int lane = t & 31;
        int v[UN];
#pragma unroll
        for (int u = 0; u < UN; ++u) v[u] = adj[(w0 + u) * 32 + lane];
#pragma unroll
        for (int u = 0; u < UN; ++u) {
            unsigned bal = __ballot_sync(0xffffffffu, v[u] > 0);
            if (lane == 0) g_mask[w0 + u] = bal;
        }
    } else if (b < 37120) {
        int i = (b - 32768) * 256 + t;   // float4 index
        float4 v;
        float4* dst;
        if (i < 1048576) { v = ((const float4*)x)[i]; dst = &((float4*)g_xr)[i]; }
        else { v = ((const float4*)W)[i - 1048576]; dst = &((float4*)g_Wr)[i - 1048576]; }
        v.x = __uint_as_float(tf32r(v.x));
        v.y = __uint_as_float(tf32r(v.y));
        v.z = __uint_as_float(tf32r(v.z));
        v.w = __uint_as_float(tf32r(v.w));
        *dst = v;
    } else {
        int idx = b - 37120;             // 0..31
        if (idx == 0 && t < HEADS) g_f2maxU[t] = 0u;   // below all encodings
        int h = idx >> 2;
        int k = (idx & 3) * 128 + (t >> 1);
        int dh = (t & 1) * 32;
        const float* wrow = W + h * (DIN * DOUT) + k * 64 + dh;
        const float* a1p = a1 + h * 64 + dh;
        const float* a2p = a2 + h * 64 + dh;
        float s1 = 0.f, s2 = 0.f;
#pragma unroll
        for (int d = 0; d < 32; ++d) {
            float w = wrow[d];
            s1 = fmaf(w, a1p[d], s1);
            s2 = fmaf(w, a2p[d], s2);
        }
        s1 += __shfl_xor_sync(0xffffffffu, s1, 1);
        s2 += __shfl_xor_sync(0xffffffffu, s2, 1);
        if ((t & 1) == 0) g_w12[h * 512 + k] = make_float2(s1, s2);
    }
}

// ---------------- kernel 2: Wh GEMM via tf32 mma, fused fp16/perm16 epilogue
#define XSTR 20
#define WSTR 72
__global__ __launch_bounds__(256, 2) void gemm_wh2_kernel() {
    __shared__ __align__(16) float buf[2 * 128 * XSTR + 2 * 16 * WSTR];
    float* xS = buf;                    // [2][128][20]
    float* wS = buf + 2 * 128 * XSTR;   // [2][16][72]
    __half* Csh = (__half*)buf;         // epilogue overlay [64][136]

    const int h = blockIdx.y, row0 = blockIdx.x * 128, t = threadIdx.x;
    const int lane = t & 31, warp = t >> 5, gid = lane >> 2, tig = lane & 3;
    const int mbase = (warp & 3) * 16, nbase = (warp >> 2) * 64;

    float acc[8][4];
#pragma unroll
    for (int nc = 0; nc < 8; ++nc)
#pragma unroll
        for (int q = 0; q < 4; ++q) acc[nc][q] = 0.f;

    const int sj = t >> 1, sk8 = (t & 1) * 8;
    const int wk = t >> 4, wd = (t & 15) * 4;
#define GSTAGE(it, b) do {                                                    \
        const float* xsrc = &g_xr[(long long)(row0 + sj) * 512 + (it) * 16];  \
        cp16(&xS[(b) * 2560 + sj * XSTR + sk8],     xsrc + sk8);              \
        cp16(&xS[(b) * 2560 + sj * XSTR + sk8 + 4], xsrc + sk8 + 4);          \
        cp16(&wS[(b) * 1152 + wk * WSTR + wd],                                \
             &g_Wr[h * (DIN * DOUT) + ((it) * 16 + wk) * 64 + wd]);           \
    } while (0)

    GSTAGE(0, 0); cp_commit();

    for (int it = 0; it < 32; ++it) {
        const int cur = it & 1;
        cp_wait<0>();
        __syncthreads();
        if (it + 1 < 32) GSTAGE(it + 1, cur ^ 1);
        cp_commit();
        const float* xb = xS + cur * 2560;
        const float* wb = wS + cur * 1152;
#pragma unroll
        for (int k8 = 0; k8 < 2; ++k8) {
            const int k0 = k8 * 8;
            const unsigned a0 = __float_as_uint(wb[(k0 + tig) * WSTR + mbase + gid]);
            const unsigned a1 = __float_as_uint(wb[(k0 + tig) * WSTR + mbase + gid + 8]);
            const unsigned a2 = __float_as_uint(wb[(k0 + tig + 4) * WSTR + mbase + gid]);
            const unsigned a3 = __float_as_uint(wb[(k0 + tig + 4) * WSTR + mbase + gid + 8]);
#pragma unroll
            for (int nc = 0; nc < 8; ++nc) {
                const int j = nbase + nc * 8 + gid;
                const unsigned b0 = __float_as_uint(xb[j * XSTR + k0 + tig]);
                const unsigned b1 = __float_as_uint(xb[j * XSTR + k0 + tig + 4]);
                mma_tf32(acc[nc], a0, a1, a2, a3, b0, b1);
            }
        }
    }
    __syncthreads();

#pragma unroll
    for (int nc = 0; nc < 8; ++nc) {
        const int j = nbase + nc * 8 + tig * 2;
        *(__half2*)&Csh[(mbase + gid) * 136 + j] =
            __floats2half2_rn(acc[nc][0], acc[nc][1]);
        *(__half2*)&Csh[(mbase + gid + 8) * 136 + j] =
            __floats2half2_rn(acc[nc][2], acc[nc][3]);
    }
    __syncthreads();

#pragma unroll
    for (int s = 0; s < 4; ++s) {
        int id = t + s * 256;
        int d = id >> 4, c8 = id & 15;
        __half hbuf[8];
#pragma unroll
        for (int e = 0; e < 8; ++e) {
            int p = c8 * 8 + e;
            int pl = p & 15;
            int u = ((pl >> 2) & 3) * 2 + ((pl >> 1) & 1) * 8 + (pl & 1);
            hbuf[e] = Csh[d * 136 + (p & ~15) + u];
        }
        *(uint4*)&g_WhH[((long long)(h * 64 + d)) * NN + row0 + c8 * 8] =
            *(uint4*)hbuf;
    }
}

// ---------------- kernel 2c: f1/f2 = x @ w12 (+ fused f2max atomics) --------
__global__ __launch_bounds__(256) void f1f2_kernel(const float* __restrict__ x) {
    __shared__ float w1s[8 * 512], w2s[8 * 512];
    __shared__ float wmaxS[8][8];   // [warp][head]
    const int t = threadIdx.x, lane = t & 31, warp = t >> 5;
    for (int i = t; i < 8 * 512; i += 256) {
        float2 v = g_w12[i];
        w1s[i] = v.x; w2s[i] = v.y;
    }
    __syncthreads();
    float wmax[8];
#pragma unroll
    for (int h = 0; h < 8; ++h) wmax[h] = -3.4e38f;

    for (int it = 0; it < 4; ++it) {
        const int node = blockIdx.x * 32 + warp * 4 + it;
        float4 xv[4];
#pragma unroll
        for (int q = 0; q < 4; ++q)
            xv[q] = ((const float4*)x)[(long long)node * 128 + lane + 32 * q];
        float f1r[8], f2r[8];
#pragma unroll
        for (int h = 0; h < 8; ++h) {
            float s1 = 0.f, s2 = 0.f;
#pragma unroll
            for (int q = 0; q < 4; ++q) {
                float4 w1 = *(const float4*)&w1s[h * 512 + 4 * lane + 128 * q];
                float4 w2 = *(const float4*)&w2s[h * 512 + 4 * lane + 128 * q];
                s1 = fmaf(xv[q].x, w1.x, s1); s1 = fmaf(xv[q].y, w1.y, s1);
                s1 = fmaf(xv[q].z, w1.z, s1); s1 = fmaf(xv[q].w, w1.w, s1);
                s2 = fmaf(xv[q].x, w2.x, s2); s2 = fmaf(xv[q].y, w2.y, s2);
                s2 = fmaf(xv[q].z, w2.z, s2); s2 = fmaf(xv[q].w, w2.w, s2);
            }
            f1r[h] = s1; f2r[h] = s2;
        }
#pragma unroll
        for (int s = 16; s; s >>= 1)
#pragma unroll
            for (int h = 0; h < 8; ++h) {
                f1r[h] += __shfl_xor_sync(0xffffffffu, f1r[h], s);
                f2r[h] += __shfl_xor_sync(0xffffffffu, f2r[h], s);
            }
#pragma unroll
        for (int h = 0; h < 8; ++h)
            wmax[h] = fmaxf(wmax[h], f2r[h] * L2E);
        if (lane == 0)
#pragma unroll
            for (int h = 0; h < 8; ++h) {
                g_f1[h * NN + node] = f1r[h] * L2E;
                g_f2[h * NN + node] = f2r[h] * L2E;
            }
    }
    // block-reduce per-head max across warps, then one atomic per head
    if (lane == 0)
#pragma unroll
        for (int h = 0; h < 8; ++h) wmaxS[warp][h] = wmax[h];
    __syncthreads();
    if (t < 8) {
        float m = wmaxS[0][t];
#pragma unroll
        for (int w = 1; w < 8; ++w) m = fmaxf(m, wmaxS[w][t]);
        atomicMax(&g_f2maxU[t], fenc(m));
    }
}

// ---------------- kernel 2e: precompute A,C (2^12-scaled) and B,D (perm16) --
__global__ __launch_bounds__(256) void prep_kernel() {
    int h = blockIdx.y;
    int i = blockIdx.x * 256 + threadIdx.x;
    float f2m = fdec(g_f2maxU[h]);
    float f1 = g_f1[h * NN + i];
    float e = f1 + f2m;
    float m = fmaxf(e, 0.2f * e);
    g_AC[h * NN + i] =
        make_float2(ex2f(e - m + PSCALE), ex2f(0.2f * e - m + PSCALE));
    float dd = g_f2[h * NN + i] - f2m;
    int u = i & 15;
    int pos = ((u & 7) >> 1) * 4 + ((u >> 3) & 1) * 2 + (u & 1);
    g_BD[h * NN + (i & ~15) + pos] = make_float2(ex2f(dd), ex2f(0.2f * dd));
}

// ---------------- kernel 3: attention (fp16 k16 mma, no exp in loop) --------
// r11/r13 measured-best structure — unchanged.
__global__ __launch_bounds__(256, 2) void attn_kernel(float* __restrict__ out) {
    __shared__ __align__(16) __half   WhS[3][64 * 72];
    __shared__ __align__(16) float2   bdS[3][64];
    __shared__ __align__(16) unsigned maskS[3][512];

    const int h = blockIdx.y, row0 = blockIdx.x * 256, t = threadIdx.x;
    const int lane = t & 31, warp = t >> 5, gid = lane >> 2, tig = lane & 3;
    const int rbase = warp * 32 + gid;

    ull ACp[4];
#pragma unroll
    for (int r = 0; r < 4; ++r) {
        float2 ac = g_AC[h * NN + row0 + rbase + r * 8];
        ACp[r] = pack2f(ac.x, ac.y);
    }

    float acc[2][8][4];
    float accL[2][4];
#pragma unroll
    for (int b = 0; b < 2; ++b) {
#pragma unroll
        for (int nc = 0; nc < 8; ++nc)
#pragma unroll
            for (int q = 0; q < 4; ++q) acc[b][nc][q] = 0.f;
#pragma unroll
        for (int q = 0; q < 4; ++q) accL[b][q] = 0.f;
    }

    const int sd = t >> 2, sc = t & 3;
#define STAGE(jt, b) do {                                                     \
        long long js = (long long)(jt) * 64;                                  \
        const __half* srow = &g_WhH[((long long)(h * 64 + sd)) * NN + js];    \
        cp16(&WhS[b][sd * 72 + sc * 16],     srow + sc * 16);                 \
        cp16(&WhS[b][sd * 72 + sc * 16 + 8], srow + sc * 16 + 8);             \
        cp8(&maskS[b][t * 2],                                                 \
            &g_mask[(long long)(row0 + t) * MWORDS + (jt) * 2]);              \
        if (t < 32) cp16(&bdS[b][t * 2], &g_BD[h * NN + js + t * 2]);         \
    } while (0)

    STAGE(0, 0); cp_commit();
    STAGE(1, 1); cp_commit();

    int cur = 0;
    for (int jt = 0; jt < 128; ++jt) {
        cp_wait<1>();
        __syncthreads();

        unsigned mw0[4], mw1[4];
#pragma unroll
        for (int r = 0; r < 4; ++r) {
            mw0[r] = maskS[cur][(rbase + r * 8) * 2];
            mw1[r] = maskS[cur][(rbase + r * 8) * 2 + 1];
        }
        const __half* whb = &WhS[cur][gid * 72 + tig * 4];
        const float2* bdb = &bdS[cur][tig * 4];

#pragma unroll
        for (int ks = 0; ks < 4; ++ks) {
            const ulonglong2 bdv = *(const ulonglong2*)(bdb + ks * 16);
            const ulonglong2 bdw = *(const ulonglong2*)(bdb + ks * 16 + 2);
            const int sh = ((ks & 1) << 4) + 2 * tig;
            unsigned fa[4][2];
#pragma unroll
            for (int r = 0; r < 4; ++r) {
                const unsigned x = ((ks < 2) ? mw0[r] : mw1[r]) >> sh;
                float p0 = maxmul(ACp[r], bdv.x);
                float p1 = maxmul(ACp[r], bdv.y);
                float p2 = maxmul(ACp[r], bdw.x);
                float p3 = maxmul(ACp[r], bdw.y);
                if (!(x & 1u))     p0 = 0.f;
                if (!(x & 2u))     p1 = 0.f;
                if (!(x & 0x100u)) p2 = 0.f;
                if (!(x & 0x200u)) p3 = 0.f;
                fa[r][0] = pack16(p1, p0);
                fa[r][1] = pack16(p3, p2);
            }
#pragma unroll
            for (int nc = 0; nc < 8; ++nc) {
                const uint2 bb = *(const uint2*)(whb + nc * 576 + ks * 16);
                mma_f16(acc[0][nc], fa[0][0], fa[1][0], fa[0][1], fa[1][1],
                        bb.x, bb.y);
                mma_f16(acc[1][nc], fa[2][0], fa[3][0], fa[2][1], fa[3][1],
                        bb.x, bb.y);
            }
            mma_f16(accL[0], fa[0][0], fa[1][0], fa[0][1], fa[1][1], ONE2, ONE2);
            mma_f16(accL[1], fa[2][0], fa[3][0], fa[2][1], fa[3][1], ONE2, ONE2);
        }

        if (jt < 126) {
            int nb = cur >= 1 ? cur - 1 : cur + 2;   // (jt+2)%3
            STAGE(jt + 2, nb);
        }
        cp_commit();
        cur = (cur == 2) ? 0 : cur + 1;
    }

#pragma unroll
    for (int b = 0; b < 2; ++b) {
        const float invLo = 1.0f / accL[b][0];
        const float invHi = 1.0f / accL[b][2];
        const long long ga = row0 + rbase + b * 16;
        const long long gb = ga + 8;
#pragma unroll
        for (int nc = 0; nc < 8; ++nc) {
            const int col = h * 64 + nc * 8 + tig * 2;
            ((float2*)out)[(ga * 512 + col) >> 1] =
                make_float2(acc[b][nc][0] * invLo, acc[b][nc][1] * invLo);
            ((float2*)out)[(gb * 512 + col) >> 1] =
                make_float2(acc[b][nc][2] * invHi, acc[b][nc][3] * invHi);
        }
    }
}

// ---------------- launch ----------------
extern "C" void kernel_launch(void* const* d_in, const int* in_sizes, int n_in,
                              void* d_out, int out_size) {
    const float* x   = (const float*)d_in[0];
    const int*   adj = (const int*)d_in[1];
    const float* W   = (const float*)d_in[2];
    const float* a1  = (const float*)d_in[3];
    const float* a2  = (const float*)d_in[4];
    float* out = (float*)d_out;

    fused_prep_kernel<<<37152, 256>>>(adj, x, W, a1, a2);
    gemm_wh2_kernel<<<dim3(NN / 128, HEADS), 256>>>();
    f1f2_kernel<<<NN / 32, 256>>>(x);
    prep_kernel<<<dim3(NN / 256, HEADS), 256>>>();
    attn_kernel<<<dim3(NN / 256, HEADS), 256>>>(out);
}